// round 1
// baseline (speedup 1.0000x reference)
#include <cuda_runtime.h>
#include <cuda_bf16.h>

#define D 64
#define NU_CONST 100001
#define NI_CONST 200001
#define NMAX (NU_CONST + NI_CONST)

// Scratch ping-pong buffers (zero-init .bss, no allocation).
__device__ float g_buf_a[(size_t)NMAX * D];
__device__ float g_buf_b[(size_t)NMAX * D];

// ---------------------------------------------------------------------------
// init: out = cur = concat(user_emb, item_emb); nxt = 0
// operates on float4 granularity (all boundaries divisible by 4 floats)
// ---------------------------------------------------------------------------
__global__ void init_kernel(const float4* __restrict__ ue,
                            const float4* __restrict__ ie,
                            float4* __restrict__ out,
                            float4* __restrict__ cur,
                            float4* __restrict__ nxt,
                            int n_user_v4, int n_total_v4) {
    int i = blockIdx.x * blockDim.x + threadIdx.x;
    if (i >= n_total_v4) return;
    float4 v = (i < n_user_v4) ? ue[i] : ie[i - n_user_v4];
    out[i] = v;
    cur[i] = v;
    nxt[i] = make_float4(0.f, 0.f, 0.f, 0.f);
}

// ---------------------------------------------------------------------------
// SpMM: y[row[e]] += vals[e] * x[col[e]]   (edge-parallel, 16 lanes per edge,
// one float4 vector-atomic per lane -> 16 red-ops per 256B row)
// ---------------------------------------------------------------------------
__global__ void spmm_kernel(const int* __restrict__ row,
                            const int* __restrict__ col,
                            const float* __restrict__ vals,
                            const float* __restrict__ x,
                            float* __restrict__ y,
                            int n_edges) {
    int t = blockIdx.x * blockDim.x + threadIdx.x;
    int e = t >> 4;          // half-warp (16 lanes) per edge
    int l = t & 15;          // lane within edge: handles 4 consecutive floats
    if (e >= n_edges) return;
    int   r = row[e];
    int   c = col[e];
    float v = vals[e];
    const float4 xv = *reinterpret_cast<const float4*>(x + (size_t)c * D + l * 4);
    float4 add = make_float4(v * xv.x, v * xv.y, v * xv.z, v * xv.w);
    atomicAdd(reinterpret_cast<float4*>(y + (size_t)r * D + l * 4), add);
}

// ---------------------------------------------------------------------------
// accum: out += nxt; zero the retired buffer (becomes next layer's target)
// ---------------------------------------------------------------------------
__global__ void accum_kernel(float4* __restrict__ out,
                             const float4* __restrict__ nxt,
                             float4* __restrict__ zero_me,
                             int n_v4) {
    int i = blockIdx.x * blockDim.x + threadIdx.x;
    if (i >= n_v4) return;
    float4 o = out[i];
    float4 n = nxt[i];
    o.x += n.x; o.y += n.y; o.z += n.z; o.w += n.w;
    out[i] = o;
    zero_me[i] = make_float4(0.f, 0.f, 0.f, 0.f);
}

// ---------------------------------------------------------------------------
// final: out = (out + nxt) * 0.25   (mean over 4 layer outputs)
// ---------------------------------------------------------------------------
__global__ void final_kernel(float4* __restrict__ out,
                             const float4* __restrict__ nxt,
                             int n_v4) {
    int i = blockIdx.x * blockDim.x + threadIdx.x;
    if (i >= n_v4) return;
    float4 o = out[i];
    float4 n = nxt[i];
    o.x = (o.x + n.x) * 0.25f;
    o.y = (o.y + n.y) * 0.25f;
    o.z = (o.z + n.z) * 0.25f;
    o.w = (o.w + n.w) * 0.25f;
    out[i] = o;
}

extern "C" void kernel_launch(void* const* d_in, const int* in_sizes, int n_in,
                              void* d_out, int out_size) {
    // Inputs (metadata order = setup_inputs dict order):
    // 0: user_emb f32 [n_users*64]
    // 1: item_emb f32 [n_items*64]
    // 2: row  i32 [E]
    // 3: col  i32 [E]
    // 4: vals f32 [E]
    // 5: n_layers (scalar, == 3)
    // 6: n_users  (scalar)
    const float* user_emb = (const float*)d_in[0];
    const float* item_emb = (const float*)d_in[1];
    const int*   row      = (const int*)d_in[2];
    const int*   col      = (const int*)d_in[3];
    const float* vals     = (const float*)d_in[4];

    const int n_users = in_sizes[0] / D;
    const int n_items = in_sizes[1] / D;
    const int n_total = n_users + n_items;
    const int E       = in_sizes[2];
    const int n_layers = 3; // fixed by problem definition

    float* out = (float*)d_out;

    float* buf_a = nullptr;
    float* buf_b = nullptr;
    cudaGetSymbolAddress((void**)&buf_a, g_buf_a);
    cudaGetSymbolAddress((void**)&buf_b, g_buf_b);

    const int n_v4      = n_total * (D / 4);       // total float4 elements
    const int n_user_v4 = n_users * (D / 4);

    const int TB = 256;

    float* cur = buf_a;
    float* nxt = buf_b;

    // init: out = cur = x0; nxt = 0
    init_kernel<<<(n_v4 + TB - 1) / TB, TB>>>(
        (const float4*)user_emb, (const float4*)item_emb,
        (float4*)out, (float4*)cur, (float4*)nxt, n_user_v4, n_v4);

    for (int layer = 0; layer < n_layers; layer++) {
        // nxt = L * cur (atomic scatter)
        long long nthreads = (long long)E * 16;
        int nblocks = (int)((nthreads + TB - 1) / TB);
        spmm_kernel<<<nblocks, TB>>>(row, col, vals, cur, nxt, E);

        if (layer + 1 < n_layers) {
            // out += nxt; zero cur (it becomes the next scatter target); swap
            accum_kernel<<<(n_v4 + TB - 1) / TB, TB>>>(
                (float4*)out, (const float4*)nxt, (float4*)cur, n_v4);
            float* t = cur; cur = nxt; nxt = t;
        } else {
            // fold final mean: out = (out + nxt) / 4
            final_kernel<<<(n_v4 + TB - 1) / TB, TB>>>(
                (float4*)out, (const float4*)nxt, n_v4);
        }
    }
}

// round 4
// speedup vs baseline: 2.5306x; 2.5306x over previous
#include <cuda_runtime.h>
#include <cuda_bf16.h>

#define D 64
#define NU_MAX 100001
#define NI_MAX 200001
#define NMAX (NU_MAX + NI_MAX)
#define PMAX 3200000
#define SCAN_BLK 1024

// Scratch (.bss, no allocation).
__device__ float g_buf_a[(size_t)NMAX * D];
__device__ float g_buf_b[(size_t)NMAX * D];
__device__ int   g_u_ptr[NU_MAX + 2];
__device__ int   g_i_ptr[NI_MAX + 2];
__device__ int   g_i_work[NI_MAX + 2];
__device__ int   g_cnt[NI_MAX + 2];
__device__ int   g_bsums[512];
__device__ int   g_tcol[PMAX];
__device__ float g_tval[PMAX];

// ---------------------------------------------------------------------------
// init: out = cur = concat(user_emb, item_emb); also zero the item counters.
// ---------------------------------------------------------------------------
__global__ void init_kernel(const float4* __restrict__ ue,
                            const float4* __restrict__ ie,
                            float4* __restrict__ out,
                            float4* __restrict__ cur,
                            int* __restrict__ cnt,
                            int n_user_v4, int n_total_v4, int n_cnt) {
    int i = blockIdx.x * blockDim.x + threadIdx.x;
    if (i < n_cnt) cnt[i] = 0;
    if (i >= n_total_v4) return;
    float4 v = (i < n_user_v4) ? ue[i] : ie[i - n_user_v4];
    out[i] = v;
    cur[i] = v;
}

// ---------------------------------------------------------------------------
// u_ptr[r] = lower_bound(row[0:P], r)   (first half of row[] is sorted)
// ---------------------------------------------------------------------------
__global__ void build_uptr_kernel(const int* __restrict__ row, int P,
                                  int* __restrict__ uptr, int n_users) {
    int r = blockIdx.x * blockDim.x + threadIdx.x;
    if (r > n_users) return;
    int lo = 0, hi = P;
    while (lo < hi) {
        int mid = (lo + hi) >> 1;
        if (row[mid] < r) lo = mid + 1; else hi = mid;
    }
    uptr[r] = lo;
}

// ---------------------------------------------------------------------------
// count item degrees from first-half cols (col[e] = item + n_users)
// ---------------------------------------------------------------------------
__global__ void count_kernel(const int* __restrict__ col, int P,
                             int* __restrict__ cnt, int n_users) {
    int e = blockIdx.x * blockDim.x + threadIdx.x;
    if (e >= P) return;
    atomicAdd(&cnt[col[e] - n_users], 1);
}

// ---------------------------------------------------------------------------
// exclusive scan of cnt[0:n] -> ptr  (3 passes)
// ---------------------------------------------------------------------------
__global__ void scan1_kernel(const int* __restrict__ cnt, int* __restrict__ ptr,
                             int* __restrict__ bsums, int n) {
    __shared__ int sh[SCAN_BLK];
    int i = blockIdx.x * SCAN_BLK + threadIdx.x;
    int v = (i < n) ? cnt[i] : 0;
    sh[threadIdx.x] = v;
    __syncthreads();
    for (int off = 1; off < SCAN_BLK; off <<= 1) {
        int t = 0;
        if ((int)threadIdx.x >= off) t = sh[threadIdx.x - off];
        __syncthreads();
        sh[threadIdx.x] += t;
        __syncthreads();
    }
    if (i < n) ptr[i] = sh[threadIdx.x] - v;   // exclusive
    if (threadIdx.x == SCAN_BLK - 1) bsums[blockIdx.x] = sh[SCAN_BLK - 1];
}

__global__ void scan2_kernel(int* __restrict__ bsums, int nb) {
    __shared__ int sh[512];
    int v = ((int)threadIdx.x < nb) ? bsums[threadIdx.x] : 0;
    sh[threadIdx.x] = v;
    __syncthreads();
    for (int off = 1; off < 512; off <<= 1) {
        int t = 0;
        if ((int)threadIdx.x >= off) t = sh[threadIdx.x - off];
        __syncthreads();
        sh[threadIdx.x] += t;
        __syncthreads();
    }
    if ((int)threadIdx.x < nb) bsums[threadIdx.x] = sh[threadIdx.x] - v;  // exclusive
}

__global__ void scan3_kernel(int* __restrict__ ptr, int* __restrict__ work,
                             const int* __restrict__ bsums, int n) {
    int i = blockIdx.x * blockDim.x + threadIdx.x;
    if (i >= n) return;
    int p = ptr[i] + bsums[i >> 10];
    ptr[i] = p;
    work[i] = p;
}

// ---------------------------------------------------------------------------
// scatter first-half edges into item-CSC (transpose): tcol = u, tval = vals
// ---------------------------------------------------------------------------
__global__ void scatter_kernel(const int* __restrict__ row,
                               const int* __restrict__ col,
                               const float* __restrict__ vals, int P,
                               int* __restrict__ iwork,
                               int* __restrict__ tcol,
                               float* __restrict__ tval, int n_users) {
    int e = blockIdx.x * blockDim.x + threadIdx.x;
    if (e >= P) return;
    int it = col[e] - n_users;
    int pos = atomicAdd(&iwork[it], 1);
    tcol[pos] = row[e];
    tval[pos] = vals[e];
}

// ---------------------------------------------------------------------------
// Row-parallel fused SpMM: 16 lanes per row, atomic-free.
//   acc = sum_e v[e] * x[c[e]]
//   intermediate: y[r] = acc; out[r] += acc
//   final:        out[r] = (out[r] + acc) * 0.25
// ---------------------------------------------------------------------------
__global__ void spmm_csr_kernel(const float* __restrict__ x,
                                float* __restrict__ y,
                                float* __restrict__ out,
                                const int* __restrict__ col1,
                                const float* __restrict__ val1,
                                const int* __restrict__ uptr,
                                const int* __restrict__ iptr,
                                const int* __restrict__ tcol,
                                const float* __restrict__ tval,
                                int n_users, int n_total, int final_mode) {
    int t = blockIdx.x * blockDim.x + threadIdx.x;
    int r = t >> 4;
    int lane = t & 15;
    if (r >= n_total) return;

    const int* cs;
    const float* vs;
    int s, e;
    if (r < n_users) {
        s = uptr[r]; e = uptr[r + 1]; cs = col1; vs = val1;
    } else {
        int ii = r - n_users;
        s = iptr[ii]; e = iptr[ii + 1]; cs = tcol; vs = tval;
    }

    float4 acc = make_float4(0.f, 0.f, 0.f, 0.f);
    int ei = s;
    // 4-way unrolled: 4 independent gathers in flight
    for (; ei + 4 <= e; ei += 4) {
        int c0 = cs[ei], c1 = cs[ei + 1], c2 = cs[ei + 2], c3 = cs[ei + 3];
        float v0 = vs[ei], v1 = vs[ei + 1], v2 = vs[ei + 2], v3 = vs[ei + 3];
        float4 x0 = *reinterpret_cast<const float4*>(x + (size_t)c0 * D + lane * 4);
        float4 x1 = *reinterpret_cast<const float4*>(x + (size_t)c1 * D + lane * 4);
        float4 x2 = *reinterpret_cast<const float4*>(x + (size_t)c2 * D + lane * 4);
        float4 x3 = *reinterpret_cast<const float4*>(x + (size_t)c3 * D + lane * 4);
        acc.x = fmaf(v0, x0.x, acc.x); acc.y = fmaf(v0, x0.y, acc.y);
        acc.z = fmaf(v0, x0.z, acc.z); acc.w = fmaf(v0, x0.w, acc.w);
        acc.x = fmaf(v1, x1.x, acc.x); acc.y = fmaf(v1, x1.y, acc.y);
        acc.z = fmaf(v1, x1.z, acc.z); acc.w = fmaf(v1, x1.w, acc.w);
        acc.x = fmaf(v2, x2.x, acc.x); acc.y = fmaf(v2, x2.y, acc.y);
        acc.z = fmaf(v2, x2.z, acc.z); acc.w = fmaf(v2, x2.w, acc.w);
        acc.x = fmaf(v3, x3.x, acc.x); acc.y = fmaf(v3, x3.y, acc.y);
        acc.z = fmaf(v3, x3.z, acc.z); acc.w = fmaf(v3, x3.w, acc.w);
    }
    for (; ei < e; ei++) {
        int c = cs[ei];
        float v = vs[ei];
        float4 xv = *reinterpret_cast<const float4*>(x + (size_t)c * D + lane * 4);
        acc.x = fmaf(v, xv.x, acc.x); acc.y = fmaf(v, xv.y, acc.y);
        acc.z = fmaf(v, xv.z, acc.z); acc.w = fmaf(v, xv.w, acc.w);
    }

    size_t o = (size_t)r * D + lane * 4;
    if (!final_mode) {
        *reinterpret_cast<float4*>(y + o) = acc;
        float4 ov = *reinterpret_cast<float4*>(out + o);
        ov.x += acc.x; ov.y += acc.y; ov.z += acc.z; ov.w += acc.w;
        *reinterpret_cast<float4*>(out + o) = ov;
    } else {
        float4 ov = *reinterpret_cast<float4*>(out + o);
        ov.x = (ov.x + acc.x) * 0.25f;
        ov.y = (ov.y + acc.y) * 0.25f;
        ov.z = (ov.z + acc.z) * 0.25f;
        ov.w = (ov.w + acc.w) * 0.25f;
        *reinterpret_cast<float4*>(out + o) = ov;
    }
}

extern "C" void kernel_launch(void* const* d_in, const int* in_sizes, int n_in,
                              void* d_out, int out_size) {
    const float* user_emb = (const float*)d_in[0];
    const float* item_emb = (const float*)d_in[1];
    const int*   row      = (const int*)d_in[2];
    const int*   col      = (const int*)d_in[3];
    const float* vals     = (const float*)d_in[4];

    const int n_users = in_sizes[0] / D;
    const int n_items = in_sizes[1] / D;
    const int n_total = n_users + n_items;
    const int E       = in_sizes[2];
    const int P       = E / 2;          // first half = user rows (sorted)

    float* out = (float*)d_out;

    float *buf_a, *buf_b;
    int *u_ptr, *i_ptr, *i_work, *cnt, *bsums, *tcol;
    float *tval;
    cudaGetSymbolAddress((void**)&buf_a, g_buf_a);
    cudaGetSymbolAddress((void**)&buf_b, g_buf_b);
    cudaGetSymbolAddress((void**)&u_ptr, g_u_ptr);
    cudaGetSymbolAddress((void**)&i_ptr, g_i_ptr);
    cudaGetSymbolAddress((void**)&i_work, g_i_work);
    cudaGetSymbolAddress((void**)&cnt, g_cnt);
    cudaGetSymbolAddress((void**)&bsums, g_bsums);
    cudaGetSymbolAddress((void**)&tcol, g_tcol);
    cudaGetSymbolAddress((void**)&tval, g_tval);

    const int TB = 256;
    const int n_v4 = n_total * (D / 4);
    const int n_user_v4 = n_users * (D / 4);
    const int n_cnt = n_items + 1;            // cnt[n_items] stays 0 -> i_ptr[n_items]=P

    // 1. init: out = cur = x0; zero item counters
    init_kernel<<<(n_v4 + TB - 1) / TB, TB>>>(
        (const float4*)user_emb, (const float4*)item_emb,
        (float4*)out, (float4*)buf_a, cnt, n_user_v4, n_v4, n_cnt);

    // 2. user CSR pointers (binary search over sorted first half)
    build_uptr_kernel<<<(n_users + 1 + TB - 1) / TB, TB>>>(row, P, u_ptr, n_users);

    // 3. item degrees
    count_kernel<<<(P + TB - 1) / TB, TB>>>(col, P, cnt, n_users);

    // 4. exclusive scan -> i_ptr (and working copy)
    int n_scan = n_cnt;                       // n_items + 1 entries
    int nb = (n_scan + SCAN_BLK - 1) / SCAN_BLK;
    scan1_kernel<<<nb, SCAN_BLK>>>(cnt, i_ptr, bsums, n_scan);
    scan2_kernel<<<1, 512>>>(bsums, nb);
    scan3_kernel<<<(n_scan + TB - 1) / TB, TB>>>(i_ptr, i_work, bsums, n_scan);

    // 5. scatter transpose (item CSC): tcol = u, tval = vals
    scatter_kernel<<<(P + TB - 1) / TB, TB>>>(row, col, vals, P, i_work, tcol, tval, n_users);

    // 6. three fused SpMM layers (atomic-free)
    int rows_threads = n_total * 16;
    int spmm_blocks = (rows_threads + TB - 1) / TB;
    // layer 0: x = buf_a(x0) -> buf_b, out += 
    spmm_csr_kernel<<<spmm_blocks, TB>>>(buf_a, buf_b, out, col, vals,
                                         u_ptr, i_ptr, tcol, tval,
                                         n_users, n_total, 0);
    // layer 1: x = buf_b -> buf_a, out +=
    spmm_csr_kernel<<<spmm_blocks, TB>>>(buf_b, buf_a, out, col, vals,
                                         u_ptr, i_ptr, tcol, tval,
                                         n_users, n_total, 0);
    // layer 2 (final): x = buf_a, out = (out + acc) * 0.25
    spmm_csr_kernel<<<spmm_blocks, TB>>>(buf_a, nullptr, out, col, vals,
                                         u_ptr, i_ptr, tcol, tval,
                                         n_users, n_total, 1);
}